// round 14
// baseline (speedup 1.0000x reference)
#include <cuda_runtime.h>
#include <cstdint>

typedef unsigned long long u64;

#define HW 3136  // 56*56

__device__ __forceinline__ u64 pack2(float a, float b) {
    u64 r; asm("mov.b64 %0, {%1,%2};" : "=l"(r) : "f"(a), "f"(b)); return r;
}
__device__ __forceinline__ float2 unpack2(u64 a) {
    float2 r; asm("mov.b64 {%0,%1}, %2;" : "=f"(r.x), "=f"(r.y) : "l"(a)); return r;
}
__device__ __forceinline__ u64 fma2(u64 a, u64 b, u64 c) {
    u64 d; asm("fma.rn.f32x2 %0, %1, %2, %3;" : "=l"(d) : "l"(a), "l"(b), "l"(c)); return d;
}
__device__ __forceinline__ void cpa16(uint32_t dst, const void* src) {
    asm volatile("cp.async.cg.shared.global [%0], [%1], 16;" :: "r"(dst), "l"(src));
}
__device__ __forceinline__ void cpa_commit() { asm volatile("cp.async.commit_group;" ::: "memory"); }
__device__ __forceinline__ void cpa_wait0()  { asm volatile("cp.async.wait_group 0;"  ::: "memory"); }
__device__ __forceinline__ void stcs4(float* p, float4 v) {
    asm volatile("st.global.cs.v4.f32 [%0], {%1,%2,%3,%4};"
                 :: "l"(p), "f"(v.x), "f"(v.y), "f"(v.z), "f"(v.w) : "memory");
}

#define NSLOT 11                  // slots 0..9 = rows m0-2..m0+7 (clamped); slot 10 = row 55
#define CCH 4                     // channels per chunk (2 kk)
#define XS_BUF (CCH * NSLOT * 56) // 2464 floats per buffer
#define NLOAD (CCH * NSLOT * 14)  // 616 float4 per chunk

// ---------------------------------------------------------------------------
// Fused: block = (l, 8-row m chunk). 224 threads = (wp:28, mp:4, h:2).
// Phase 1: x staged via double-buffered per-thread cp.async (r9 loader);
//   thread owns 2 w x 2 m x 4 j; 4 row-preloads per kk as LDS.64 (u64 pair
//   feeds fma2 directly); interior rows reused across (m,tap) in registers.
// T tile aliased over xs after phase 1 (pitch 64). Phase 2: n-packed f32x2
//   3-tap conv along w; .cs streaming stores. 6 blocks/SM, ~27.4 KB smem.
// ---------------------------------------------------------------------------
__global__ __launch_bounds__(224, 6) void fused(const float* __restrict__ x,
                                                const float* __restrict__ w1,
                                                const float* __restrict__ w2,
                                                float* __restrict__ out) {
    __shared__ __align__(16) float xsts[2 * XS_BUF];  // 19712 B; Ts (16384 B) aliases this
    __shared__ u64 w1p[768];                          //  6144 B  (w,w) dup pairs
    __shared__ u64 w2d[192];                          //  1536 B  (w,w) dup pairs
    float* Ts = xsts;

    int tid = threadIdx.x;
    int m0  = blockIdx.x * 8;
    int l   = blockIdx.y;

    // ---- weights ----
    for (int i = tid; i < 768; i += 224) { float w = w1[i]; w1p[i] = pack2(w, w); }
    if (tid < 192) { float w = w2[tid]; w2d[tid] = pack2(w, w); }

    // ---- phase-1 thread decode: (wp, mp, h) ----
    int wp = tid % 28;            // w pair -> w0 = 2*wp
    int mp = (tid / 28) % 4;      // m pair -> m = m0 + 2*mp + e
    int h  = tid / 112;           // i-half
    int w0 = wp * 2;
    int mb = m0 + 2 * mp;

    // 4 preload row slots (slot s holds row m0-2+s clamped; slot 10 = row 55).
    // hp==0 (needs wrap row 55) occurs only when m0==0 at logical slot 1.
    int rs[4];
#pragma unroll
    for (int r = 0; r < 4; r++) {
        int s = 2 * mp + r;
        rs[r] = (m0 == 0 && s == 1) ? 10 : s;
    }
    // validity per (e, tap): hp = mb+e+tap-1 in [0,56)
    bool val[2][3];
#pragma unroll
    for (int e = 0; e < 2; e++)
#pragma unroll
        for (int t = 0; t < 3; t++) {
            int hp = mb + e + t - 1;
            val[e][t] = (hp >= 0) && (hp < 56);
        }

    // ---- cooperative loader precompute (r9): 616 float4, 3 slots/thread ----
    const float* xl = x + (size_t)l * 128 * HW;
    int  goff[3];
    int  soff[3];
    bool lv[3];
#pragma unroll
    for (int k = 0; k < 3; k++) {
        int idx = tid + k * 224;
        lv[k] = idx < NLOAD;
        int ii = lv[k] ? idx : 0;
        int c  = ii / (NSLOT * 14);
        int r  = ii % (NSLOT * 14);
        int s  = r / 14;
        int wf = r % 14;
        int row = (s == 10) ? 55 : min(max(m0 - 2 + s, 0), 55);
        goff[k] = c * HW + row * 56 + wf * 4;
        soff[k] = ((c * NSLOT + s) * 56 + wf * 4) * 4;
    }
    uint32_t xsb[2] = { (uint32_t)__cvta_generic_to_shared(&xsts[0]),
                        (uint32_t)__cvta_generic_to_shared(&xsts[XS_BUF]) };

    u64 acc[2][4];  // [e][j], each = (w0, w0+1) packed pair
#pragma unroll
    for (int e = 0; e < 2; e++)
#pragma unroll
        for (int j = 0; j < 4; j++) acc[e][j] = 0ull;

    // prefetch chunk 0
#pragma unroll
    for (int k = 0; k < 3; k++)
        if (lv[k]) cpa16(xsb[0] + soff[k], xl + goff[k]);
    cpa_commit();

    // ---- phase 1: 32 chunks of 4 channels (2 kk each) ----
    for (int ch = 0; ch < 32; ch++) {
        cpa_wait0();
        __syncthreads();               // data visible; prev buf free (orders w1p/w2d too)
        if (ch < 31) {
            const float* cb = xl + (size_t)(ch + 1) * CCH * HW;
            uint32_t sb = xsb[(ch + 1) & 1];
#pragma unroll
            for (int k = 0; k < 3; k++)
                if (lv[k]) cpa16(sb + soff[k], cb + goff[k]);
            cpa_commit();
        }
        const float* xb = &xsts[(ch & 1) * XS_BUF];
#pragma unroll
        for (int kl = 0; kl < 2; kl++) {
            int kk = ch * 2 + kl;
            int cl = 2 * kl + h;       // channel within chunk for this i-half
            const float* cbase = &xb[cl * (NSLOT * 56) + w0];

            // preload 4 rows as packed (w0, w0+1) pairs
            u64 R[4];
#pragma unroll
            for (int r = 0; r < 4; r++)
                R[r] = *reinterpret_cast<const u64*>(cbase + rs[r] * 56);

#pragma unroll
            for (int t = 0; t < 3; t++) {
                ulonglong2 wa = *reinterpret_cast<const ulonglong2*>(&w1p[kk * 12 + t * 4]);
                ulonglong2 wb = *reinterpret_cast<const ulonglong2*>(&w1p[kk * 12 + t * 4 + 2]);
                if (val[0][t]) {
                    acc[0][0] = fma2(R[t], wa.x, acc[0][0]);
                    acc[0][1] = fma2(R[t], wa.y, acc[0][1]);
                    acc[0][2] = fma2(R[t], wb.x, acc[0][2]);
                    acc[0][3] = fma2(R[t], wb.y, acc[0][3]);
                }
                if (val[1][t]) {
                    acc[1][0] = fma2(R[t + 1], wa.x, acc[1][0]);
                    acc[1][1] = fma2(R[t + 1], wa.y, acc[1][1]);
                    acc[1][2] = fma2(R[t + 1], wb.x, acc[1][2]);
                    acc[1][3] = fma2(R[t + 1], wb.y, acc[1][3]);
                }
            }
        }
    }

    // ---- all xs reads done -> alias Ts over it ----
    __syncthreads();

    // edge zeroing: cols {0..3, 60..63} of 64 rows (pitch 64)
    for (int i2 = tid; i2 < 512; i2 += 224) {
        int r = i2 >> 3, c = i2 & 7;
        Ts[r * 64 + (c < 4 ? c : 56 + c)] = 0.0f;
    }
    // write T tile: Ts[(2mp+e)*8 + h*4+j][4 + w0], one float2 per (e,j)
#pragma unroll
    for (int e = 0; e < 2; e++)
#pragma unroll
        for (int j = 0; j < 4; j++) {
            float2 v = unpack2(acc[e][j]);
            *reinterpret_cast<float2*>(
                &Ts[((2 * mp + e) * 8 + h * 4 + j) * 64 + 4 + w0]) = v;
        }
    __syncthreads();

    // ---- phase 2: thread = (nq:14, mloc:8, jh:2); n = 4nq..4nq+3, 16 j, 4 oo ----
    int nq   = tid % 14;
    int mloc = (tid / 14) % 8;
    int jh   = tid / 112;
    int n0   = nq * 4;

    float* ob = out + (size_t)l * 128 * HW + (m0 + mloc) * 56 + n0;

#pragma unroll
    for (int oo = 0; oo < 4; oo++) {
        // shifted n-pairs P[i2][k'] = (t[k'], t[k'+1]), k' = 0..4
        u64 P[2][5];
#pragma unroll
        for (int i2 = 0; i2 < 2; i2++) {
            const float* r = &Ts[(mloc * 8 + i2 * 4 + oo) * 64 + 3 + n0];
            float t0 = r[0], t1 = r[1], t2 = r[2], t3 = r[3], t4 = r[4], t5 = r[5];
            P[i2][0] = pack2(t0, t1);
            P[i2][1] = pack2(t1, t2);
            P[i2][2] = pack2(t2, t3);
            P[i2][3] = pack2(t3, t4);
            P[i2][4] = pack2(t4, t5);
        }

#pragma unroll 4
        for (int jj = 0; jj < 16; jj++) {
            int j = jh * 16 + jj;
            u64 rrA = 0ull, rrB = 0ull;
#pragma unroll
            for (int i2 = 0; i2 < 2; i2++) {
                u64 wk0 = w2d[i2 * 96 + j];
                u64 wk1 = w2d[i2 * 96 + 32 + j];
                u64 wk2 = w2d[i2 * 96 + 64 + j];
                rrA = fma2(P[i2][0], wk0, rrA);
                rrA = fma2(P[i2][1], wk1, rrA);
                rrA = fma2(P[i2][2], wk2, rrA);
                rrB = fma2(P[i2][2], wk0, rrB);
                rrB = fma2(P[i2][3], wk1, rrB);
                rrB = fma2(P[i2][4], wk2, rrB);
            }
            float2 eA = unpack2(rrA);
            float2 eB = unpack2(rrB);
            stcs4(ob + (size_t)(4 * j + oo) * HW, make_float4(eA.x, eA.y, eB.x, eB.y));
        }
    }
}

// ---------------------------------------------------------------------------
extern "C" void kernel_launch(void* const* d_in, const int* in_sizes, int n_in,
                              void* d_out, int out_size) {
    const float* x  = nullptr;
    const float* w1 = nullptr;
    const float* w2 = nullptr;
    for (int i = 0; i < n_in; i++) {
        if (in_sizes[i] == 128 * 128 * 56 * 56) x  = (const float*)d_in[i];
        else if (in_sizes[i] == 64 * 3 * 4)     w1 = (const float*)d_in[i];
        else if (in_sizes[i] == 2 * 3 * 32)     w2 = (const float*)d_in[i];
    }
    if (!x)  x  = (const float*)d_in[0];
    if (!w1) w1 = (const float*)d_in[1];
    if (!w2) w2 = (const float*)d_in[2];

    fused<<<dim3(7, 128), 224>>>(x, w1, w2, (float*)d_out);
}